// round 14
// baseline (speedup 1.0000x reference)
#include <cuda_runtime.h>
#include <cstdint>
#include <math.h>

#define N_DET   10647
#define N_L0    8112            // 52*52*3
#define N_L01   10140           // + 26*26*3
#define N_CLS   20
#define NC_CAP  768             // per-class capacity (mean ~532, sd ~22.5 -> +10 sigma)
#define NWC     12              // max mask words per row (global stride)
#define MROW    13              // padded smem row stride (words)
#define NBLK    148
#define NTHR    512
#define DET_PB  72              // 148*72 = 10656 >= N_DET

// ---------------- static device scratch ----------------
__device__ float4 g_boxes[N_DET];                          // all_bbox (/416), original order
__device__ int    g_clsCount[N_CLS];                       // zero at load; reset at kernel end
__device__ unsigned long long g_clskeys[N_CLS * NC_CAP];   // (~score_bits)<<32 | orig_idx
__device__ float4 g_sbox[N_CLS * NC_CAP];                  // class-sorted boxes
__device__ float  g_sarea[N_CLS * NC_CAP];
__device__ unsigned long long g_gmask[(size_t)N_CLS * NC_CAP * NWC];  // 1.47 MB (L2)
__device__ unsigned long long g_bar1 = 0, g_bar2 = 0, g_bar3 = 0;     // monotonic barriers

__device__ __forceinline__ float sigmoidf_(float x) { return 1.0f / (1.0f + expf(-x)); }

// monotonic-counter grid barrier; one counter per site. All NBLK blocks co-resident
// (148 blocks <= 148 SMs even at 1 block/SM; ~105KB smem targets 2/SM).
__device__ __forceinline__ void grid_barrier(unsigned long long* ctr, int tid)
{
    __syncthreads();
    if (tid == 0) {
        __threadfence();
        unsigned long long ticket = atomicAdd(ctr, 1ull) + 1ull;
        unsigned long long target = ((ticket + (NBLK - 1)) / NBLK) * NBLK;
        while (atomicAdd(ctr, 0ull) < target) { __nanosleep(64); }
        __threadfence();
    }
    __syncthreads();
}

__device__ __forceinline__ void decode_one(int gid,
                                           const float* __restrict__ p0,
                                           const float* __restrict__ p1,
                                           const float* __restrict__ p2,
                                           float* __restrict__ out)
{
    const float AW[9] = {4.f, 8.f, 12.f, 3.f, 6.f, 8.f, 3.5f, 5.f, 8.f};
    const float AH[9] = {6.f, 12.f, 10.f, 7.f, 8.f, 6.f, 5.f, 4.5f, 8.f};

    const float* p; int W, HW, a, hw, base_d, ai0; float s;
    if (gid < N_L0) {
        int r = gid;          p = p0; W = 52; HW = 2704; a = r / 2704; hw = r - a * 2704;
        base_d = 0;     ai0 = 0; s = 8.f;
    } else if (gid < N_L01) {
        int r = gid - N_L0;   p = p1; W = 26; HW = 676;  a = r / 676;  hw = r - a * 676;
        base_d = N_L0;  ai0 = 3; s = 16.f;
    } else {
        int r = gid - N_L01;  p = p2; W = 13; HW = 169;  a = r / 169;  hw = r - a * 169;
        base_d = N_L01; ai0 = 6; s = 32.f;
    }
    int d = base_d + hw * 3 + a;               // detection index (reference order)

    float gx = (float)(hw % W), gy = (float)(hw / W);
    float aw = AW[ai0 + a], ah = AH[ai0 + a];
    if (hw == HW - 1) { aw = 0.f; ah = 0.f; }  // reference zeroes last hw row

    const float* base = p + hw;                 // batch 0 only
    float obj = base[(size_t)a * HW];

    float l[20];
    #pragma unroll
    for (int c = 0; c < 20; c++) l[c] = base[(size_t)(3 + 20 * a + c) * HW];
    float m = l[0]; int am = 0;
    #pragma unroll
    for (int c = 1; c < 20; c++) { if (l[c] > m) { m = l[c]; am = c; } }
    float den = 0.f;
    #pragma unroll
    for (int c = 0; c < 20; c++) den += expf(l[c] - m);
    float score = sigmoidf_(obj) / den;         // sigmoid(obj) * softmax@argmax

    float tx = base[(size_t)(63 + 4 * a + 0) * HW];
    float ty = base[(size_t)(63 + 4 * a + 1) * HW];
    float tw = base[(size_t)(63 + 4 * a + 2) * HW];
    float th = base[(size_t)(63 + 4 * a + 3) * HW];
    float cx = sigmoidf_(tx) + gx;
    float cy = sigmoidf_(ty) + gy;
    float hx = expf(tw) * aw * 0.5f;
    float hy = expf(th) * ah * 0.5f;
    float x1 = ((cx - hx) * s) / 416.0f;
    float y1 = ((cy - hy) * s) / 416.0f;
    float x2 = ((cx + hx) * s) / 416.0f;
    float y2 = ((cy + hy) * s) / 416.0f;

    g_boxes[d] = make_float4(x1, y1, x2, y2);

    unsigned long long key =
        (((unsigned long long)(~__float_as_uint(score))) << 32) | (unsigned)d;
    int slot = atomicAdd(&g_clsCount[am], 1);
    if (slot < NC_CAP) g_clskeys[am * NC_CAP + slot] = key;

    float4 ob;
    ob.x = fminf(fmaxf(x1 * 416.0f, 0.f), 415.f) / 416.0f;
    ob.y = fminf(fmaxf(y1 * 416.0f, 0.f), 415.f) / 416.0f;
    ob.z = fminf(fmaxf(x2 * 416.0f, 0.f), 415.f) / 416.0f;
    ob.w = fminf(fmaxf(y2 * 416.0f, 0.f), 415.f) / 416.0f;
    reinterpret_cast<float4*>(out)[d] = ob;
    out[4 * N_DET + d] = score;
    out[5 * N_DET + d] = (float)am;
}

// ---- fused: decode(148) -> sort(20) -> mask(148, 7-8 slices/class) -> reduce(20) ----
__global__ void __launch_bounds__(NTHR, 2) fused_kernel(const float* __restrict__ p0,
                                                        const float* __restrict__ p1,
                                                        const float* __restrict__ p2,
                                                        float* __restrict__ out)
{
    extern __shared__ unsigned long long smask[];          // NC_CAP*MROW words (~80 KB)
    __shared__ unsigned long long skey[NC_CAP];
    __shared__ float4 sb[NC_CAP];
    __shared__ float  bar[NC_CAP];
    __shared__ int    sorig[NC_CAP];
    __shared__ unsigned long long svb[NWC], srem[NWC];
    __shared__ unsigned long long diagT[64];
    __shared__ unsigned long long scand, sorall, skeptbits;

    int tid = threadIdx.x;
    int b   = blockIdx.x;
    int c   = b % N_CLS;                                    // class this block serves
    float* out_keep = out + 6 * N_DET;

    // ---- phase A: decode, 72 detections per block (all 148 blocks) ----
    {
        int gid = b * DET_PB + tid;
        if (tid < DET_PB && gid < N_DET) decode_one(gid, p0, p1, p2, out);
    }
    grid_barrier(&g_bar1, tid);

    int n = min(g_clsCount[c], NC_CAP);
    int nw = (n + 63) >> 6;

    // ---- phase B: blocks 0..19 rank-sort their class, publish sorted boxes ----
    if (b < N_CLS) {
        for (int k = tid; k < n; k += NTHR) skey[k] = g_clskeys[c * NC_CAP + k];
        if (tid < NWC) { svb[tid] = 0ull; srem[tid] = 0ull; }
        __syncthreads();

        // rank sort, warp-per-row (keys unique -> rank is a permutation); staged in smask
        unsigned long long* skey_s = smask;
        int wid = tid >> 5, lane = tid & 31;
        for (int k = wid; k < n; k += NTHR / 32) {
            unsigned long long kk = skey[k];
            int cnt = 0;
            for (int j = lane; j < n; j += 32)
                cnt += (skey[j] < kk);
            cnt = __reduce_add_sync(0xffffffffu, cnt);
            if (lane == 0) skey_s[cnt] = kk;
        }
        __syncthreads();

        for (int k = tid; k < n; k += NTHR) {
            unsigned long long key = skey_s[k];
            int orig = (int)(unsigned)key;
            float4 bx = g_boxes[orig];
            float area = (bx.z - bx.x) * (bx.w - bx.y);
            sb[k] = bx; bar[k] = area; sorig[k] = orig;
            g_sbox[c * NC_CAP + k]  = bx;
            g_sarea[c * NC_CAP + k] = area;
            float score = __uint_as_float(~(unsigned)(key >> 32));
            if (score >= 0.001f)
                atomicOr(&svb[k >> 6], 1ull << (k & 63));
        }
        __syncthreads();
    }
    grid_barrier(&g_bar2, tid);

    // ---- phase C: mask build, all 148 blocks; slice sl = b/20 of class c's tasks ----
    {
        if (b >= N_CLS) {       // sorter blocks already hold sb/bar in smem
            for (int k = tid; k < n; k += NTHR) {
                sb[k]  = g_sbox[c * NC_CAP + k];
                bar[k] = g_sarea[c * NC_CAP + k];
            }
        }
        __syncthreads();
        int sl  = b / N_CLS;
        int nsl = (c < (NBLK % N_CLS)) ? (NBLK / N_CLS + 1) : (NBLK / N_CLS);
        int ntask = nw * n;
        for (int idx = sl * NTHR + tid; idx < ntask; idx += nsl * NTHR) {
            int w = idx / n;
            int k = idx - w * n;
            if ((k >> 6) > w) continue;            // row k owns words >= k>>6 only
            float4 bk = sb[k];
            float ai = bar[k];
            unsigned long long word = 0ull;
            int jbase = w << 6;
            int jend = min(64, n - jbase);
            int jstart = (k >= jbase) ? (k - jbase + 1) : 0;
            #pragma unroll 4
            for (int jj = jstart; jj < jend; jj++) {
                float4 bj = sb[jbase + jj];
                float dx = fminf(bk.z, bj.z) - fmaxf(bk.x, bj.x);
                float dy = fminf(bk.w, bj.w) - fmaxf(bk.y, bj.y);
                float inter = fmaxf(1e-28f, dx) * fmaxf(1e-28f, dy);
                float s_ab = ai + bar[jbase + jj];
                // necessary filter (margin >> 4ulp, never rejects a true hit);
                // survivors take the reference's exact IEEE division path
                if (3.0f * inter > 0.999f * s_ab) {
                    float iou = inter / (s_ab - inter);
                    if (iou > 0.5f) word |= (1ull << jj);
                }
            }
            g_gmask[((size_t)c * NC_CAP + k) * NWC + w] = word;
        }
    }

    // ---- barrier 3; non-reducer blocks arrive and exit ----
    __syncthreads();
    if (b >= N_CLS) {
        if (tid == 0) { __threadfence(); atomicAdd(&g_bar3, 1ull); }
        return;
    }
    if (tid == 0) {
        __threadfence();
        unsigned long long ticket = atomicAdd(&g_bar3, 1ull) + 1ull;
        unsigned long long target = ((ticket + (NBLK - 1)) / NBLK) * NBLK;
        while (atomicAdd(&g_bar3, 0ull) < target) { __nanosleep(64); }
        __threadfence();
    }
    __syncthreads();

    // ---- phase D: blocks 0..19 copy class mask to smem, chunked greedy reduce ----
    for (int idx = tid; idx < n * nw; idx += NTHR) {
        int k = idx / nw;
        int w = idx - k * nw;
        if (w >= (k >> 6))
            smask[(size_t)k * MROW + w] = g_gmask[((size_t)c * NC_CAP + k) * NWC + w];
    }
    __syncthreads();

    for (int t = 0; t < nw; t++) {
        int base = t << 6;
        if (tid == 0) { scand = svb[t] & ~srem[t]; sorall = 0ull; }
        __syncthreads();
        unsigned long long cand = scand;
        // parallel load of candidates' within-chunk diag words + OR-reduce
        if (tid < 64) {
            unsigned long long myd = 0ull;
            if ((cand >> tid) & 1ull) {
                myd = smask[(size_t)(base + tid) * MROW + t];
                if (myd) atomicOr(&sorall, myd);
            }
            diagT[tid] = myd;
        }
        __syncthreads();
        if (tid == 0) {
            unsigned long long orall = sorall;
            if ((orall & cand) == 0ull) {
                // fast path: no candidate suppresses another candidate -> keep all
                skeptbits = cand;
            } else {
                // serial fallback on contiguous diagT
                unsigned long long r = srem[t], vm = svb[t];
                unsigned long long kept = 0ull;
                unsigned long long cc = cand;
                while (cc) {
                    int bb = __ffsll((long long)cc) - 1;
                    kept |= (1ull << bb);
                    r |= diagT[bb];
                    unsigned long long hi = (bb == 63) ? 0ull : (~0ull << (bb + 1));
                    cc = vm & ~r & hi;
                }
                skeptbits = kept;
            }
        }
        __syncthreads();
        unsigned long long keptbits = skeptbits;
        // scatter keep flags for this chunk (original order)
        if (tid < 64) {
            int k = base + tid;
            if (k < n) out_keep[sorig[k]] = (float)((keptbits >> tid) & 1ull);
        }
        // OR kept rows' future words into srem
        int rem_w = nw - t - 1;
        if (keptbits && rem_w > 0) {
            for (int idx = tid; idx < 64 * rem_w; idx += NTHR) {
                int q = idx / rem_w;
                if ((keptbits >> q) & 1ull) {
                    int w = t + 1 + (idx - q * rem_w);
                    unsigned long long v = smask[(size_t)(base + q) * MROW + w];
                    if (v) atomicOr(&srem[w], v);
                }
            }
        }
        __syncthreads();
    }

    // restore invariant for next replay
    if (tid == 0) g_clsCount[c] = 0;
}

// ---------------- launch ----------------
extern "C" void kernel_launch(void* const* d_in, const int* in_sizes, int n_in,
                              void* d_out, int out_size)
{
    const float* p0 = (const float*)d_in[0];   // (64, 75, 52, 52)
    const float* p1 = (const float*)d_in[1];   // (64, 75, 26, 26)
    const float* p2 = (const float*)d_in[2];   // (64, 75, 13, 13)
    float* out = (float*)d_out;                // [bboxes 4N | scores N | cls N | keep N]

    const int dyn = NC_CAP * MROW * (int)sizeof(unsigned long long);   // 79872 B
    cudaFuncSetAttribute(fused_kernel,
                         cudaFuncAttributeMaxDynamicSharedMemorySize, dyn);

    fused_kernel<<<NBLK, NTHR, dyn>>>(p0, p1, p2, out);
}

// round 15
// speedup vs baseline: 1.1198x; 1.1198x over previous
#include <cuda_runtime.h>
#include <cstdint>
#include <math.h>

#define N_DET   10647
#define N_L0    8112            // 52*52*3
#define N_L01   10140           // + 26*26*3
#define N_CLS   20
#define NC_CAP  768             // per-class capacity (mean ~532, sd ~22.5 -> +10 sigma)
#define NWC     12              // mask words per row (NC_CAP/64)
#define MROW    13              // padded smem row stride (words, odd -> conflict-free)
#define NBLK    74
#define NTHR    1024
#define DET_PB  144             // 74*144 = 10656 >= N_DET

// ---------------- static device scratch ----------------
__device__ float4 g_boxes[N_DET];                          // all_bbox (/416), original order
__device__ int    g_clsCount[N_CLS];                       // zero at load; reset at kernel end
__device__ unsigned long long g_clskeys[N_CLS * NC_CAP];   // (~score_bits)<<32 | orig_idx
__device__ unsigned long long g_gmask[(size_t)N_CLS * NC_CAP * NWC];  // 1.47 MB (L2)
__device__ unsigned long long g_bar1 = 0;                  // monotonic full-grid barrier
__device__ unsigned long long g_done[N_CLS];               // monotonic per-class done counters

__device__ __forceinline__ float sigmoidf_(float x) { return 1.0f / (1.0f + expf(-x)); }

// monotonic-counter full-grid barrier; all NBLK blocks co-resident (74 <= 148 SMs, 1/SM).
// Poll with volatile loads (no LTS atomic-ALU serialization).
__device__ __forceinline__ void grid_barrier(unsigned long long* ctr, int tid)
{
    __syncthreads();
    if (tid == 0) {
        unsigned long long ticket = atomicAdd(ctr, 1ull) + 1ull;
        unsigned long long target = ((ticket + (NBLK - 1)) / NBLK) * NBLK;
        while (*(volatile unsigned long long*)ctr < target) { __nanosleep(32); }
        __threadfence();
    }
    __syncthreads();
}

__device__ __forceinline__ void decode_one(int gid,
                                           const float* __restrict__ p0,
                                           const float* __restrict__ p1,
                                           const float* __restrict__ p2,
                                           float* __restrict__ out)
{
    const float AW[9] = {4.f, 8.f, 12.f, 3.f, 6.f, 8.f, 3.5f, 5.f, 8.f};
    const float AH[9] = {6.f, 12.f, 10.f, 7.f, 8.f, 6.f, 5.f, 4.5f, 8.f};

    const float* p; int W, HW, a, hw, base_d, ai0; float s;
    if (gid < N_L0) {
        int r = gid;          p = p0; W = 52; HW = 2704; a = r / 2704; hw = r - a * 2704;
        base_d = 0;     ai0 = 0; s = 8.f;
    } else if (gid < N_L01) {
        int r = gid - N_L0;   p = p1; W = 26; HW = 676;  a = r / 676;  hw = r - a * 676;
        base_d = N_L0;  ai0 = 3; s = 16.f;
    } else {
        int r = gid - N_L01;  p = p2; W = 13; HW = 169;  a = r / 169;  hw = r - a * 169;
        base_d = N_L01; ai0 = 6; s = 32.f;
    }
    int d = base_d + hw * 3 + a;               // detection index (reference order)

    float gx = (float)(hw % W), gy = (float)(hw / W);
    float aw = AW[ai0 + a], ah = AH[ai0 + a];
    if (hw == HW - 1) { aw = 0.f; ah = 0.f; }  // reference zeroes last hw row

    const float* base = p + hw;                 // batch 0 only
    float obj = base[(size_t)a * HW];

    float l[20];
    #pragma unroll
    for (int c = 0; c < 20; c++) l[c] = base[(size_t)(3 + 20 * a + c) * HW];
    float m = l[0]; int am = 0;
    #pragma unroll
    for (int c = 1; c < 20; c++) { if (l[c] > m) { m = l[c]; am = c; } }
    float den = 0.f;
    #pragma unroll
    for (int c = 0; c < 20; c++) den += expf(l[c] - m);
    float score = sigmoidf_(obj) / den;         // sigmoid(obj) * softmax@argmax

    float tx = base[(size_t)(63 + 4 * a + 0) * HW];
    float ty = base[(size_t)(63 + 4 * a + 1) * HW];
    float tw = base[(size_t)(63 + 4 * a + 2) * HW];
    float th = base[(size_t)(63 + 4 * a + 3) * HW];
    float cx = sigmoidf_(tx) + gx;
    float cy = sigmoidf_(ty) + gy;
    float hx = expf(tw) * aw * 0.5f;
    float hy = expf(th) * ah * 0.5f;
    float x1 = ((cx - hx) * s) / 416.0f;
    float y1 = ((cy - hy) * s) / 416.0f;
    float x2 = ((cx + hx) * s) / 416.0f;
    float y2 = ((cy + hy) * s) / 416.0f;

    g_boxes[d] = make_float4(x1, y1, x2, y2);

    unsigned long long key =
        (((unsigned long long)(~__float_as_uint(score))) << 32) | (unsigned)d;
    int slot = atomicAdd(&g_clsCount[am], 1);
    if (slot < NC_CAP) g_clskeys[am * NC_CAP + slot] = key;

    float4 ob;
    ob.x = fminf(fmaxf(x1 * 416.0f, 0.f), 415.f) / 416.0f;
    ob.y = fminf(fmaxf(y1 * 416.0f, 0.f), 415.f) / 416.0f;
    ob.z = fminf(fmaxf(x2 * 416.0f, 0.f), 415.f) / 416.0f;
    ob.w = fminf(fmaxf(y2 * 416.0f, 0.f), 415.f) / 416.0f;
    reinterpret_cast<float4*>(out)[d] = ob;
    out[4 * N_DET + d] = score;
    out[5 * N_DET + d] = (float)am;
}

// ---- fused: decode(74) -> [grid bar] -> sort(74, redundant) + mask(74, sliced)
//      -> [per-class done counters] -> reduce(20) ----
__global__ void __launch_bounds__(NTHR, 1) fused_kernel(const float* __restrict__ p0,
                                                        const float* __restrict__ p1,
                                                        const float* __restrict__ p2,
                                                        float* __restrict__ out)
{
    extern __shared__ unsigned long long smask[];          // NC_CAP*MROW words (~80 KB)
    __shared__ unsigned long long skey[NC_CAP];
    __shared__ float4 sb[NC_CAP];
    __shared__ float  bar[NC_CAP];
    __shared__ int    sorig[NC_CAP];
    __shared__ unsigned long long svb[NWC], srem[NWC];
    __shared__ unsigned long long diagT[64];
    __shared__ unsigned long long scand, sorall, skeptbits;

    int tid = threadIdx.x;
    int b   = blockIdx.x;
    int c   = b % N_CLS;                                    // class this block serves
    int sl  = b / N_CLS;                                    // slice index within the class
    int nsl = (c < (NBLK % N_CLS)) ? (NBLK / N_CLS + 1) : (NBLK / N_CLS);
    float* out_keep = out + 6 * N_DET;

    // ---- phase A: decode, 144 detections per block (all 74 blocks) ----
    {
        int gid = b * DET_PB + tid;
        if (tid < DET_PB && gid < N_DET) {
            decode_one(gid, p0, p1, p2, out);
            __threadfence();                    // order this thread's global writes
        }
    }
    grid_barrier(&g_bar1, tid);

    // ---- phase B (all blocks, redundant per class): rank-sort + gather to local smem ----
    int n = min(g_clsCount[c], NC_CAP);
    int nw = (n + 63) >> 6;
    if (tid < n) skey[tid] = g_clskeys[c * NC_CAP + tid];
    if (tid < NWC) { svb[tid] = 0ull; srem[tid] = 0ull; }
    __syncthreads();

    {   // rank sort, warp-per-row (keys unique -> rank is a permutation); staged in smask
        unsigned long long* skey_s = smask;
        int wid = tid >> 5, lane = tid & 31;
        for (int k = wid; k < n; k += NTHR / 32) {
            unsigned long long kk = skey[k];
            int cnt = 0;
            for (int j = lane; j < n; j += 32)
                cnt += (skey[j] < kk);
            cnt = __reduce_add_sync(0xffffffffu, cnt);
            if (lane == 0) skey_s[cnt] = kk;
        }
        __syncthreads();
        if (tid < n) {
            unsigned long long key = skey_s[tid];
            int orig = (int)(unsigned)key;
            float4 bx = g_boxes[orig];
            sb[tid]  = bx;
            bar[tid] = (bx.z - bx.x) * (bx.w - bx.y);
            if (b < N_CLS) {
                sorig[tid] = orig;
                float score = __uint_as_float(~(unsigned)(key >> 32));
                if (score >= 0.001f)
                    atomicOr(&svb[tid >> 6], 1ull << (tid & 63));
            }
        }
        __syncthreads();
    }

    // ---- phase C: mask build from local smem; slice sl of this class's tasks ----
    {
        int ntask = nw * n;
        for (int idx = sl * NTHR + tid; idx < ntask; idx += nsl * NTHR) {
            int w = idx / n;
            int k = idx - w * n;
            if ((k >> 6) > w) continue;            // row k owns words >= k>>6 only
            float4 bk = sb[k];
            float ai = bar[k];
            unsigned long long word = 0ull;
            int jbase = w << 6;
            int jend = min(64, n - jbase);
            int jstart = (k >= jbase) ? (k - jbase + 1) : 0;
            #pragma unroll 4
            for (int jj = jstart; jj < jend; jj++) {
                float4 bj = sb[jbase + jj];
                float dx = fminf(bk.z, bj.z) - fmaxf(bk.x, bj.x);
                float dy = fminf(bk.w, bj.w) - fmaxf(bk.y, bj.y);
                float inter = fmaxf(1e-28f, dx) * fmaxf(1e-28f, dy);
                float s_ab = ai + bar[jbase + jj];
                // necessary filter (margin >> 4ulp, never rejects a true hit);
                // survivors take the reference's exact IEEE division path
                if (3.0f * inter > 0.999f * s_ab) {
                    float iou = inter / (s_ab - inter);
                    if (iou > 0.5f) word |= (1ull << jj);
                }
            }
            g_gmask[((size_t)c * NC_CAP + k) * NWC + w] = word;
        }
        __threadfence();                           // order this thread's mask writes
    }
    __syncthreads();

    // ---- per-class completion: reducer waits ONLY for its own class's slices ----
    if (tid == 0) {
        unsigned long long t = atomicAdd(&g_done[c], 1ull) + 1ull;    // monotonic, replay-safe
        if (b < N_CLS) {
            unsigned long long tgt = ((t + (unsigned long long)nsl - 1ull) / nsl) * nsl;
            while (((volatile unsigned long long*)g_done)[c] < tgt) { __nanosleep(32); }
            __threadfence();
        }
    }
    if (b >= N_CLS) return;                        // slice-only blocks exit immediately
    __syncthreads();

    // ---- phase D: copy class mask to smem, chunked greedy reduce ----
    for (int idx = tid; idx < n * nw; idx += NTHR) {
        int k = idx / nw;
        int w = idx - k * nw;
        if (w >= (k >> 6))
            smask[(size_t)k * MROW + w] = g_gmask[((size_t)c * NC_CAP + k) * NWC + w];
    }
    __syncthreads();

    for (int t = 0; t < nw; t++) {
        int base = t << 6;
        if (tid == 0) { scand = svb[t] & ~srem[t]; sorall = 0ull; }
        __syncthreads();
        unsigned long long cand = scand;
        // parallel load of candidates' within-chunk diag words + OR-reduce
        if (tid < 64) {
            unsigned long long myd = 0ull;
            if ((cand >> tid) & 1ull) {
                myd = smask[(size_t)(base + tid) * MROW + t];
                if (myd) atomicOr(&sorall, myd);
            }
            diagT[tid] = myd;
        }
        __syncthreads();
        if (tid == 0) {
            unsigned long long orall = sorall;
            if ((orall & cand) == 0ull) {
                // fast path: no candidate suppresses another candidate -> keep all
                skeptbits = cand;
            } else {
                // serial fallback on contiguous diagT
                unsigned long long r = srem[t], vm = svb[t];
                unsigned long long kept = 0ull;
                unsigned long long cc = cand;
                while (cc) {
                    int bb = __ffsll((long long)cc) - 1;
                    kept |= (1ull << bb);
                    r |= diagT[bb];
                    unsigned long long hi = (bb == 63) ? 0ull : (~0ull << (bb + 1));
                    cc = vm & ~r & hi;
                }
                skeptbits = kept;
            }
        }
        __syncthreads();
        unsigned long long keptbits = skeptbits;
        // scatter keep flags for this chunk (original order)
        if (tid < 64) {
            int k = base + tid;
            if (k < n) out_keep[sorig[k]] = (float)((keptbits >> tid) & 1ull);
        }
        // OR kept rows' future words into srem
        int rem_w = nw - t - 1;
        if (keptbits && rem_w > 0) {
            for (int idx = tid; idx < 64 * rem_w; idx += NTHR) {
                int q = idx / rem_w;
                if ((keptbits >> q) & 1ull) {
                    int w = t + 1 + (idx - q * rem_w);
                    unsigned long long v = smask[(size_t)(base + q) * MROW + w];
                    if (v) atomicOr(&srem[w], v);
                }
            }
        }
        __syncthreads();
    }

    // restore invariant for next replay
    if (tid == 0) g_clsCount[c] = 0;
}

// ---------------- launch ----------------
extern "C" void kernel_launch(void* const* d_in, const int* in_sizes, int n_in,
                              void* d_out, int out_size)
{
    const float* p0 = (const float*)d_in[0];   // (64, 75, 52, 52)
    const float* p1 = (const float*)d_in[1];   // (64, 75, 26, 26)
    const float* p2 = (const float*)d_in[2];   // (64, 75, 13, 13)
    float* out = (float*)d_out;                // [bboxes 4N | scores N | cls N | keep N]

    const int dyn = NC_CAP * MROW * (int)sizeof(unsigned long long);   // 79872 B
    cudaFuncSetAttribute(fused_kernel,
                         cudaFuncAttributeMaxDynamicSharedMemorySize, dyn);

    fused_kernel<<<NBLK, NTHR, dyn>>>(p0, p1, p2, out);
}

// round 17
// speedup vs baseline: 1.7432x; 1.5567x over previous
#include <cuda_runtime.h>
#include <cstdint>
#include <math.h>

#define N_DET   10647
#define N_L0    8112            // 52*52*3
#define N_L01   10140           // + 26*26*3
#define N_CLS   20
#define NC_CAP  768             // per-class capacity (mean ~532, sd ~22.5 -> +10 sigma)
#define SORT_N  1024            // bitonic size (power of 2 >= NC_CAP)
#define NWC     12              // mask words per row (NC_CAP/64)
#define MROW    13              // padded smem row stride (words, odd -> conflict-free)
#define NBLK    74
#define NTHR    1024
#define DET_PB  144             // 74*144 = 10656 >= N_DET

// ---------------- static device scratch ----------------
__device__ float4 g_boxes[N_DET];                          // all_bbox (/416), original order
__device__ int    g_clsCount[N_CLS];                       // zero at load; reset at kernel end
__device__ unsigned long long g_clskeys[N_CLS * NC_CAP];   // (~score_bits)<<32 | orig_idx
__device__ unsigned long long g_gmask[(size_t)N_CLS * NC_CAP * NWC];  // 1.47 MB (L2)
__device__ unsigned long long g_bar1 = 0;                  // monotonic full-grid barrier
__device__ unsigned long long g_done[N_CLS];               // monotonic per-class done counters

__device__ __forceinline__ float sigmoidf_(float x) { return 1.0f / (1.0f + expf(-x)); }

// monotonic-counter full-grid barrier; all NBLK blocks co-resident (74 <= 148 SMs, 1/SM).
__device__ __forceinline__ void grid_barrier(unsigned long long* ctr, int tid)
{
    __syncthreads();
    if (tid == 0) {
        unsigned long long ticket = atomicAdd(ctr, 1ull) + 1ull;
        unsigned long long target = ((ticket + (NBLK - 1)) / NBLK) * NBLK;
        while (*(volatile unsigned long long*)ctr < target) { __nanosleep(32); }
        __threadfence();
    }
    __syncthreads();
}

__device__ __forceinline__ void decode_one(int gid,
                                           const float* __restrict__ p0,
                                           const float* __restrict__ p1,
                                           const float* __restrict__ p2,
                                           float* __restrict__ out)
{
    const float AW[9] = {4.f, 8.f, 12.f, 3.f, 6.f, 8.f, 3.5f, 5.f, 8.f};
    const float AH[9] = {6.f, 12.f, 10.f, 7.f, 8.f, 6.f, 5.f, 4.5f, 8.f};

    const float* p; int W, HW, a, hw, base_d, ai0; float s;
    if (gid < N_L0) {
        int r = gid;          p = p0; W = 52; HW = 2704; a = r / 2704; hw = r - a * 2704;
        base_d = 0;     ai0 = 0; s = 8.f;
    } else if (gid < N_L01) {
        int r = gid - N_L0;   p = p1; W = 26; HW = 676;  a = r / 676;  hw = r - a * 676;
        base_d = N_L0;  ai0 = 3; s = 16.f;
    } else {
        int r = gid - N_L01;  p = p2; W = 13; HW = 169;  a = r / 169;  hw = r - a * 169;
        base_d = N_L01; ai0 = 6; s = 32.f;
    }
    int d = base_d + hw * 3 + a;               // detection index (reference order)

    float gx = (float)(hw % W), gy = (float)(hw / W);
    float aw = AW[ai0 + a], ah = AH[ai0 + a];
    if (hw == HW - 1) { aw = 0.f; ah = 0.f; }  // reference zeroes last hw row

    const float* base = p + hw;                 // batch 0 only
    float obj = base[(size_t)a * HW];

    float l[20];
    #pragma unroll
    for (int c = 0; c < 20; c++) l[c] = base[(size_t)(3 + 20 * a + c) * HW];
    float m = l[0]; int am = 0;
    #pragma unroll
    for (int c = 1; c < 20; c++) { if (l[c] > m) { m = l[c]; am = c; } }
    float den = 0.f;
    #pragma unroll
    for (int c = 0; c < 20; c++) den += expf(l[c] - m);
    float score = sigmoidf_(obj) / den;         // sigmoid(obj) * softmax@argmax

    float tx = base[(size_t)(63 + 4 * a + 0) * HW];
    float ty = base[(size_t)(63 + 4 * a + 1) * HW];
    float tw = base[(size_t)(63 + 4 * a + 2) * HW];
    float th = base[(size_t)(63 + 4 * a + 3) * HW];
    float cx = sigmoidf_(tx) + gx;
    float cy = sigmoidf_(ty) + gy;
    float hx = expf(tw) * aw * 0.5f;
    float hy = expf(th) * ah * 0.5f;
    float x1 = ((cx - hx) * s) / 416.0f;
    float y1 = ((cy - hy) * s) / 416.0f;
    float x2 = ((cx + hx) * s) / 416.0f;
    float y2 = ((cy + hy) * s) / 416.0f;

    g_boxes[d] = make_float4(x1, y1, x2, y2);

    unsigned long long key =
        (((unsigned long long)(~__float_as_uint(score))) << 32) | (unsigned)d;
    int slot = atomicAdd(&g_clsCount[am], 1);
    if (slot < NC_CAP) g_clskeys[am * NC_CAP + slot] = key;

    float4 ob;
    ob.x = fminf(fmaxf(x1 * 416.0f, 0.f), 415.f) / 416.0f;
    ob.y = fminf(fmaxf(y1 * 416.0f, 0.f), 415.f) / 416.0f;
    ob.z = fminf(fmaxf(x2 * 416.0f, 0.f), 415.f) / 416.0f;
    ob.w = fminf(fmaxf(y2 * 416.0f, 0.f), 415.f) / 416.0f;
    reinterpret_cast<float4*>(out)[d] = ob;
    out[4 * N_DET + d] = score;
    out[5 * N_DET + d] = (float)am;
}

// ---- fused: decode(74) -> [grid bar] -> bitonic sort(74, redundant) + mask(74, sliced)
//      -> [per-class done counters] -> Jacobi greedy reduce(20) ----
__global__ void __launch_bounds__(NTHR, 1) fused_kernel(const float* __restrict__ p0,
                                                        const float* __restrict__ p1,
                                                        const float* __restrict__ p2,
                                                        float* __restrict__ out)
{
    extern __shared__ unsigned long long smask[];          // NC_CAP*MROW words (~80 KB)
    __shared__ unsigned long long skey[SORT_N];
    __shared__ float4 sb[NC_CAP];
    __shared__ float  bar[NC_CAP];
    __shared__ int    sorig[NC_CAP];
    __shared__ unsigned long long svb[NWC], srem[NWC];
    __shared__ unsigned long long sacc[2];
    __shared__ unsigned long long scand, skeptbits;

    int tid = threadIdx.x;
    int b   = blockIdx.x;
    int c   = b % N_CLS;                                    // class this block serves
    int sl  = b / N_CLS;                                    // slice index within the class
    int nsl = (c < (NBLK % N_CLS)) ? (NBLK / N_CLS + 1) : (NBLK / N_CLS);
    float* out_keep = out + 6 * N_DET;

    // ---- phase A: decode, 144 detections per block (all 74 blocks) ----
    {
        int gid = b * DET_PB + tid;
        if (tid < DET_PB && gid < N_DET) {
            decode_one(gid, p0, p1, p2, out);
            __threadfence();                    // order this thread's global writes
        }
    }
    grid_barrier(&g_bar1, tid);

    // ---- phase B (all blocks, redundant per class): bitonic sort + gather ----
    int n = min(g_clsCount[c], NC_CAP);
    int nw = (n + 63) >> 6;
    skey[tid] = (tid < n) ? g_clskeys[c * NC_CAP + tid] : ~0ull;   // pad sorts last
    if (tid < NWC) { svb[tid] = 0ull; srem[tid] = 0ull; }
    __syncthreads();

    // bitonic sort, 1024 elems, 512 CE/step (real keys < pad: score>0 => ~score_bits<0xFFFFFFFF)
    #pragma unroll
    for (int k = 2; k <= SORT_N; k <<= 1) {
        for (int j = k >> 1; j > 0; j >>= 1) {
            if (tid < SORT_N / 2) {
                int i = 2 * tid - (tid & (j - 1));
                int pr = i | j;
                bool up = ((i & k) == 0);
                unsigned long long A = skey[i], B = skey[pr];
                if ((A > B) == up) { skey[i] = B; skey[pr] = A; }
            }
            __syncthreads();
        }
    }

    if (tid < n) {
        unsigned long long key = skey[tid];
        int orig = (int)(unsigned)key;
        float4 bx = g_boxes[orig];
        sb[tid]  = bx;
        bar[tid] = (bx.z - bx.x) * (bx.w - bx.y);
        if (b < N_CLS) {
            sorig[tid] = orig;
            float score = __uint_as_float(~(unsigned)(key >> 32));
            if (score >= 0.001f)
                atomicOr(&svb[tid >> 6], 1ull << (tid & 63));
        }
    }
    __syncthreads();

    // ---- phase C: mask build from local smem; slice sl of this class's tasks ----
    {
        int ntask = nw * n;
        for (int idx = sl * NTHR + tid; idx < ntask; idx += nsl * NTHR) {
            int w = idx / n;
            int k = idx - w * n;
            if ((k >> 6) > w) continue;            // row k owns words >= k>>6 only
            float4 bk = sb[k];
            float ai = bar[k];
            unsigned long long word = 0ull;
            int jbase = w << 6;
            int jend = min(64, n - jbase);
            int jstart = (k >= jbase) ? (k - jbase + 1) : 0;
            #pragma unroll 4
            for (int jj = jstart; jj < jend; jj++) {
                float4 bj = sb[jbase + jj];
                float dx = fminf(bk.z, bj.z) - fmaxf(bk.x, bj.x);
                float dy = fminf(bk.w, bj.w) - fmaxf(bk.y, bj.y);
                float inter = fmaxf(1e-28f, dx) * fmaxf(1e-28f, dy);
                float s_ab = ai + bar[jbase + jj];
                // necessary filter (margin >> 4ulp, never rejects a true hit);
                // survivors take the reference's exact IEEE division path
                if (3.0f * inter > 0.999f * s_ab) {
                    float iou = inter / (s_ab - inter);
                    if (iou > 0.5f) word |= (1ull << jj);
                }
            }
            g_gmask[((size_t)c * NC_CAP + k) * NWC + w] = word;
        }
        __threadfence();                           // order this thread's mask writes
    }
    __syncthreads();

    // ---- per-class completion: reducer waits ONLY for its own class's slices ----
    if (tid == 0) {
        unsigned long long t = atomicAdd(&g_done[c], 1ull) + 1ull;    // monotonic, replay-safe
        if (b < N_CLS) {
            unsigned long long tgt = ((t + (unsigned long long)nsl - 1ull) / nsl) * nsl;
            while (((volatile unsigned long long*)g_done)[c] < tgt) { __nanosleep(32); }
            __threadfence();
        }
    }
    if (b >= N_CLS) return;                        // slice-only blocks exit immediately
    __syncthreads();

    // ---- phase D: copy class mask to smem, chunked greedy reduce (Jacobi closure) ----
    for (int idx = tid; idx < n * nw; idx += NTHR) {
        int k = idx / nw;
        int w = idx - k * nw;
        if (w >= (k >> 6))
            smask[(size_t)k * MROW + w] = g_gmask[((size_t)c * NC_CAP + k) * NWC + w];
    }
    __syncthreads();

    for (int t = 0; t < nw; t++) {
        int base = t << 6;
        if (tid == 0) { scand = svb[t] & ~srem[t]; sacc[0] = 0ull; sacc[1] = 0ull; }
        __syncthreads();
        unsigned long long cand = scand;

        // Within-chunk greedy closure via Jacobi fixed point on 64 threads:
        //   kept = cand & ~removed;  removed = OR_{i in kept} diag_i
        // Edges are strictly low->high within the chunk (DAG) => unique fixed
        // point == greedy result; converges in chain-depth iterations.
        if (tid < 64) {
            unsigned long long myd = ((cand >> tid) & 1ull)
                ? smask[(size_t)(base + tid) * MROW + t] : 0ull;
            unsigned long long removed = 0ull;
            int p = 0;
            for (int it = 0; it < 66; ++it) {
                unsigned long long kept = cand & ~removed;
                unsigned long long contrib = ((kept >> tid) & 1ull) ? myd : 0ull;
                unsigned lo = __reduce_or_sync(0xffffffffu, (unsigned)contrib);
                unsigned hi = __reduce_or_sync(0xffffffffu, (unsigned)(contrib >> 32));
                if ((tid & 31) == 0 && (lo | hi))
                    atomicOr(&sacc[p], ((unsigned long long)hi << 32) | lo);
                asm volatile("bar.sync 1, 64;" ::: "memory");
                unsigned long long nr = sacc[p];
                if (tid == 0) sacc[p ^ 1] = 0ull;          // prep next buffer
                asm volatile("bar.sync 1, 64;" ::: "memory");
                if (nr == removed) break;                   // stabilized
                removed = nr;
                p ^= 1;
            }
            if (tid == 0) skeptbits = cand & ~removed;
        }
        __syncthreads();
        unsigned long long keptbits = skeptbits;

        // scatter keep flags for this chunk (original order)
        if (tid < 64) {
            int k = base + tid;
            if (k < n) out_keep[sorig[k]] = (float)((keptbits >> tid) & 1ull);
        }
        // OR kept rows' future words into srem
        int rem_w = nw - t - 1;
        if (keptbits && rem_w > 0) {
            for (int idx = tid; idx < 64 * rem_w; idx += NTHR) {
                int q = idx / rem_w;
                if ((keptbits >> q) & 1ull) {
                    int w = t + 1 + (idx - q * rem_w);
                    unsigned long long v = smask[(size_t)(base + q) * MROW + w];
                    if (v) atomicOr(&srem[w], v);
                }
            }
        }
        __syncthreads();
    }

    // restore invariant for next replay
    if (tid == 0) g_clsCount[c] = 0;
}

// ---------------- launch ----------------
extern "C" void kernel_launch(void* const* d_in, const int* in_sizes, int n_in,
                              void* d_out, int out_size)
{
    const float* p0 = (const float*)d_in[0];   // (64, 75, 52, 52)
    const float* p1 = (const float*)d_in[1];   // (64, 75, 26, 26)
    const float* p2 = (const float*)d_in[2];   // (64, 75, 13, 13)
    float* out = (float*)d_out;                // [bboxes 4N | scores N | cls N | keep N]

    const int dyn = NC_CAP * MROW * (int)sizeof(unsigned long long);   // 79872 B
    cudaFuncSetAttribute(fused_kernel,
                         cudaFuncAttributeMaxDynamicSharedMemorySize, dyn);

    fused_kernel<<<NBLK, NTHR, dyn>>>(p0, p1, p2, out);
}